// round 1
// baseline (speedup 1.0000x reference)
#include <cuda_runtime.h>

#define B_ 256
#define N_ 256
#define F_ 64
#define H_ 512

// Scratch (static device globals — allocation-free per harness rules)
__device__ float g_XW1[N_ * H_];                       // 512 KB
__device__ float g_dinv[B_ * N_];                      // 256 KB
__device__ float g_normA[(size_t)B_ * N_ * N_];        // 67 MB
__device__ float g_bufA[(size_t)B_ * N_ * H_];         // 134 MB
__device__ float g_bufY[(size_t)B_ * N_ * H_];         // 134 MB

__device__ __forceinline__ float sigmoidf_(float x) {
    return 1.0f / (1.0f + expf(-x));
}

// ---------------------------------------------------------------------------
// XW1 = node_emb @ w1 + b1  (batch-invariant, 256x64 @ 64x512)
// ---------------------------------------------------------------------------
__global__ void xw1_kernel(const float* __restrict__ X,
                           const float* __restrict__ w1,
                           const float* __restrict__ b1) {
    int i = blockIdx.x;      // node row
    int h = threadIdx.x;     // hidden col (512 threads)
    __shared__ float xr[F_];
    if (h < F_) xr[h] = X[i * F_ + h];
    __syncthreads();
    float acc = b1[h];
#pragma unroll 8
    for (int k = 0; k < F_; k++) acc = fmaf(xr[k], w1[k * H_ + h], acc);
    g_XW1[i * H_ + h] = acc;
}

// ---------------------------------------------------------------------------
// d_inv_sqrt per (batch, node): D = 1 + 0.5*(rowsum+colsum of sigmoid(z)) + 1e-6
// One block per batch; smem-tiled so both row and column sums read z coalesced.
// ---------------------------------------------------------------------------
__global__ void dinv_kernel(const float* __restrict__ z) {
    int b = blockIdx.x;
    int t = threadIdx.x;     // 256 threads
    __shared__ float tile[32][N_];
    __shared__ float rs[N_];
    const float* Z = z + (size_t)b * N_ * N_;
    float cs = 0.0f;         // column sum owned by thread t (column t)
    for (int j0 = 0; j0 < N_; j0 += 32) {
#pragma unroll
        for (int r = 0; r < 32; r++) {
            float v = sigmoidf_(Z[(j0 + r) * N_ + t]);   // coalesced
            tile[r][t] = v;
            cs += v;
        }
        __syncthreads();
        int warp = t >> 5, lane = t & 31;
#pragma unroll
        for (int rr = 0; rr < 4; rr++) {
            int r = warp * 4 + rr;
            float s = 0.0f;
#pragma unroll
            for (int c = 0; c < 8; c++) s += tile[r][lane + 32 * c];
#pragma unroll
            for (int o = 16; o; o >>= 1) s += __shfl_down_sync(0xffffffffu, s, o);
            if (lane == 0) rs[j0 + r] = s;
        }
        __syncthreads();
    }
    float D = 1.0f + 0.5f * (rs[t] + cs) + 1e-6f;
    g_dinv[b * N_ + t] = rsqrtf(D);
}

// ---------------------------------------------------------------------------
// normA[b,i,j] = (0.5*(sig(z[b,i,j]) + sig(z[b,j,i])) + (i==j)) * dinv[i]*dinv[j]
// 32x32 tiles with smem transpose so the z^T read is coalesced.
// ---------------------------------------------------------------------------
__global__ void norma_kernel(const float* __restrict__ z) {
    int b = blockIdx.z;
    int i0 = blockIdx.y * 32, j0 = blockIdx.x * 32;
    int tx = threadIdx.x, ty = threadIdx.y;
    __shared__ float tT[32][33];
    const float* Z = z + (size_t)b * N_ * N_;
    tT[ty][tx] = Z[(j0 + ty) * N_ + i0 + tx];   // coalesced load of transposed block
    __syncthreads();
    int i = i0 + ty, j = j0 + tx;
    float a  = sigmoidf_(Z[i * N_ + j]);
    float at = sigmoidf_(tT[tx][ty]);           // z[b, j, i]
    float v = 0.5f * (a + at);
    if (i == j) v += 1.0f;
    v *= g_dinv[b * N_ + i] * g_dinv[b * N_ + j];
    g_normA[(size_t)b * N_ * N_ + i * N_ + j] = v;
}

// ---------------------------------------------------------------------------
// Batched GEMM: C[b](256x512) = act( A[b](256xK) @ B[b](Kx512) + bias )
//   - A always batched (stride sA), B optionally shared (stride sB == 0)
//   - lda == K, ldb == 512, ldc == 512
// Classic 128x128x8 tile, 8x8 per thread, 256 threads.
// ---------------------------------------------------------------------------
template <bool RELU, bool HASBIAS>
__global__ __launch_bounds__(256, 2) void gemm_kernel(
    const float* __restrict__ A, long sA,
    const float* __restrict__ Bm, long sB,
    const float* __restrict__ bias,
    float* __restrict__ C, int K) {
    int b = blockIdx.z;
    const float* Ab = A + (long)b * sA;
    const float* Bb = Bm + (long)b * sB;
    float* Cb = C + (long)b * (long)(N_ * H_);
    int rowBase = blockIdx.y * 128;
    int colBase = blockIdx.x * 128;

    __shared__ float As[8][128];   // As[k][m]
    __shared__ float Bs[8][128];   // Bs[k][n]

    int tid = threadIdx.x;
    int tx = tid & 15, ty = tid >> 4;
    int aRow = tid >> 1, aCol = (tid & 1) * 4;   // A: one float4 per thread
    int bRow = tid >> 5, bCol = (tid & 31) * 4;  // B: one float4 per thread

    float acc[8][8] = {};

    for (int k0 = 0; k0 < K; k0 += 8) {
        float4 av = *(const float4*)&Ab[(long)(rowBase + aRow) * K + k0 + aCol];
        float4 bv = *(const float4*)&Bb[(long)(k0 + bRow) * H_ + colBase + bCol];
        As[aCol + 0][aRow] = av.x;
        As[aCol + 1][aRow] = av.y;
        As[aCol + 2][aRow] = av.z;
        As[aCol + 3][aRow] = av.w;
        *(float4*)&Bs[bRow][bCol] = bv;
        __syncthreads();
#pragma unroll
        for (int kk = 0; kk < 8; ++kk) {
            float af[8], bf[8];
            *(float4*)&af[0] = *(const float4*)&As[kk][ty * 8];
            *(float4*)&af[4] = *(const float4*)&As[kk][ty * 8 + 4];
            *(float4*)&bf[0] = *(const float4*)&Bs[kk][tx * 8];
            *(float4*)&bf[4] = *(const float4*)&Bs[kk][tx * 8 + 4];
#pragma unroll
            for (int i = 0; i < 8; i++)
#pragma unroll
                for (int j = 0; j < 8; j++)
                    acc[i][j] = fmaf(af[i], bf[j], acc[i][j]);
        }
        __syncthreads();
    }

#pragma unroll
    for (int i = 0; i < 8; i++) {
        int row = rowBase + ty * 8 + i;
#pragma unroll
        for (int j4 = 0; j4 < 2; j4++) {
            int col = colBase + tx * 8 + j4 * 4;
            float4 v;
            float* vp = &v.x;
#pragma unroll
            for (int jj = 0; jj < 4; jj++) {
                float t = acc[i][j4 * 4 + jj];
                if (HASBIAS) t += bias[col + jj];
                if (RELU) t = fmaxf(t, 0.0f);
                vp[jj] = t;
            }
            *(float4*)&Cb[(long)row * H_ + col] = v;
        }
    }
}

// ---------------------------------------------------------------------------
// graph_emb = mean(H3, axis=1); logits = graph_emb @ fcw + fcb  (C=2)
// ---------------------------------------------------------------------------
__global__ void readout_kernel(const float* __restrict__ fcw,
                               const float* __restrict__ fcb,
                               float* __restrict__ out) {
    int b = blockIdx.x;
    int h = threadIdx.x;   // 512 threads
    const float* Hb = g_bufA + (size_t)b * N_ * H_;
    float s = 0.0f;
    for (int i = 0; i < N_; i++) s += Hb[i * H_ + h];   // coalesced across h
    float ge = s * (1.0f / N_);
    __shared__ float s0[H_], s1[H_];
    s0[h] = ge * fcw[h * 2 + 0];
    s1[h] = ge * fcw[h * 2 + 1];
    __syncthreads();
    for (int st = 256; st > 0; st >>= 1) {
        if (h < st) { s0[h] += s0[h + st]; s1[h] += s1[h + st]; }
        __syncthreads();
    }
    if (h == 0) {
        out[b * 2 + 0] = s0[0] + fcb[0];
        out[b * 2 + 1] = s1[0] + fcb[1];
    }
}

// ---------------------------------------------------------------------------
extern "C" void kernel_launch(void* const* d_in, const int* in_sizes, int n_in,
                              void* d_out, int out_size) {
    const float* z   = (const float*)d_in[0];
    const float* ne  = (const float*)d_in[1];
    const float* w1  = (const float*)d_in[2];
    const float* b1  = (const float*)d_in[3];
    const float* w2  = (const float*)d_in[4];
    const float* b2  = (const float*)d_in[5];
    const float* w3  = (const float*)d_in[6];
    const float* b3  = (const float*)d_in[7];
    const float* fcw = (const float*)d_in[8];
    const float* fcb = (const float*)d_in[9];
    float* out = (float*)d_out;

    float *pXW1 = nullptr, *pNA = nullptr, *pA = nullptr, *pY = nullptr;
    cudaGetSymbolAddress((void**)&pXW1, g_XW1);
    cudaGetSymbolAddress((void**)&pNA, g_normA);
    cudaGetSymbolAddress((void**)&pA, g_bufA);
    cudaGetSymbolAddress((void**)&pY, g_bufY);

    xw1_kernel<<<N_, H_>>>(ne, w1, b1);
    dinv_kernel<<<B_, N_>>>(z);
    norma_kernel<<<dim3(8, 8, B_), dim3(32, 32)>>>(z);

    dim3 gg(4, 2, B_);   // N tiles, M tiles, batch
    // H1 = relu(normA @ XW1)
    gemm_kernel<true,  false><<<gg, 256>>>(pNA, (long)N_ * N_, pXW1, 0, nullptr, pA, N_);
    // Y2 = H1 @ w2 + b2
    gemm_kernel<false, true ><<<gg, 256>>>(pA, (long)N_ * H_, w2, 0, b2, pY, H_);
    // H2 = relu(normA @ Y2)
    gemm_kernel<true,  false><<<gg, 256>>>(pNA, (long)N_ * N_, pY, (long)N_ * H_, nullptr, pA, N_);
    // Y3 = H2 @ w3 + b3
    gemm_kernel<false, true ><<<gg, 256>>>(pA, (long)N_ * H_, w3, 0, b3, pY, H_);
    // H3 = relu(normA @ Y3)
    gemm_kernel<true,  false><<<gg, 256>>>(pNA, (long)N_ * N_, pY, (long)N_ * H_, nullptr, pA, N_);

    readout_kernel<<<B_, H_>>>(fcw, fcb, out);
}

// round 3
// speedup vs baseline: 2.2412x; 2.2412x over previous
#include <cuda_runtime.h>
#include <cuda_bf16.h>
#include <cstdint>
#include <cstring>

#define B_ 256
#define N_ 256
#define F_ 64
#define H_ 512

// ---------------------------------------------------------------------------
// Scratch (static device globals — allocation-free per harness rules)
// bf16 hi/lo planes for error-compensated tensor-core GEMMs
// ---------------------------------------------------------------------------
__device__ __align__(16) __nv_bfloat16 g_nAhi[(size_t)B_ * N_ * N_];   // 33.5 MB
__device__ __align__(16) __nv_bfloat16 g_nAlo[(size_t)B_ * N_ * N_];
__device__ __align__(16) __nv_bfloat16 g_Hhi[(size_t)B_ * N_ * H_];    // 67 MB
__device__ __align__(16) __nv_bfloat16 g_Hlo[(size_t)B_ * N_ * H_];
__device__ __align__(16) __nv_bfloat16 g_Ythi[(size_t)B_ * H_ * N_];   // 67 MB (transposed Y)
__device__ __align__(16) __nv_bfloat16 g_Ytlo[(size_t)B_ * H_ * N_];
__device__ __align__(16) __nv_bfloat16 g_XW1thi[H_ * N_];
__device__ __align__(16) __nv_bfloat16 g_XW1tlo[H_ * N_];
__device__ __align__(16) __nv_bfloat16 g_w2thi[H_ * H_];
__device__ __align__(16) __nv_bfloat16 g_w2tlo[H_ * H_];
__device__ __align__(16) __nv_bfloat16 g_w3thi[H_ * H_];
__device__ __align__(16) __nv_bfloat16 g_w3tlo[H_ * H_];
__device__ float g_dinv[B_ * N_];
__device__ float g_meanpart[2 * B_ * H_];   // [mTile][batch][hidden] partial col sums

// ---------------------------------------------------------------------------
// Helpers (all portable PTX: sm_80-class — NO tcgen05 under this toolchain)
// ---------------------------------------------------------------------------
__device__ __forceinline__ uint32_t s2u(const void* p) {
    uint32_t a;
    asm("{ .reg .u64 t; cvta.to.shared.u64 t, %1; cvt.u32.u64 %0, t; }" : "=r"(a) : "l"(p));
    return a;
}
__device__ __forceinline__ void cpasync16(uint32_t dst, const void* src) {
    asm volatile("cp.async.cg.shared.global [%0], [%1], 16;" :: "r"(dst), "l"(src));
}
__device__ __forceinline__ void ldsm4(uint32_t addr, uint32_t* r) {
    asm volatile("ldmatrix.sync.aligned.m8n8.x4.shared.b16 {%0,%1,%2,%3}, [%4];"
                 : "=r"(r[0]), "=r"(r[1]), "=r"(r[2]), "=r"(r[3]) : "r"(addr));
}
__device__ __forceinline__ void mma16816(float* d, const uint32_t* a, const uint32_t* b) {
    asm volatile(
        "mma.sync.aligned.m16n8k16.row.col.f32.bf16.bf16.f32 "
        "{%0,%1,%2,%3}, {%4,%5,%6,%7}, {%8,%9}, {%0,%1,%2,%3};"
        : "+f"(d[0]), "+f"(d[1]), "+f"(d[2]), "+f"(d[3])
        : "r"(a[0]), "r"(a[1]), "r"(a[2]), "r"(a[3]), "r"(b[0]), "r"(b[1]));
}
__device__ __forceinline__ uint32_t pack2(__nv_bfloat16 a, __nv_bfloat16 b) {
    unsigned short ua, ub;
    memcpy(&ua, &a, 2); memcpy(&ub, &b, 2);
    return (uint32_t)ua | ((uint32_t)ub << 16);
}
__device__ __forceinline__ void split_bf(float v, __nv_bfloat16& h, __nv_bfloat16& l) {
    h = __float2bfloat16(v);
    l = __float2bfloat16(v - __bfloat162float(h));
}
__device__ __forceinline__ float sigmoidf_(float x) { return 1.0f / (1.0f + expf(-x)); }

// ---------------------------------------------------------------------------
// HMMA GEMM: C[128x128] = A(hi+lo) @ B(hi+lo)^T, K via 64-wide chunks.
// A row-major [M,KTOT]; B pre-transposed [N,KTOT] (row n = column n) so
// mma row.col consumes it with plain (non-trans) ldmatrix.
// Smem: 3 buffers x 4 planes (Ahi,Alo,Bhi,Blo) x 16KB, xor-swizzled 128B rows.
// EPI: 0 = relu + hi/lo row-major out; 1 = bias + hi/lo transposed out;
//      2 = relu + column-sum partial reduce (mean path)
// ---------------------------------------------------------------------------
constexpr int PLANE = 16384;
constexpr int BUFSZ = 4 * PLANE;                 // 64 KB
constexpr int SMEM_G = 3 * BUFSZ;                // 196608 B
constexpr int PADW = 129;

__device__ __forceinline__ void issue_chunk(uint32_t sdst,
                                            const __nv_bfloat16* a, const __nv_bfloat16* b,
                                            const __nv_bfloat16* c, const __nv_bfloat16* d,
                                            int ldk) {
#pragma unroll
    for (int i = 0; i < 4; i++) {
        size_t go = (size_t)i * 32 * ldk;
        cpasync16(sdst + i * 4096,             a + go);
        cpasync16(sdst + PLANE + i * 4096,     b + go);
        cpasync16(sdst + 2 * PLANE + i * 4096, c + go);
        cpasync16(sdst + 3 * PLANE + i * 4096, d + go);
    }
    asm volatile("cp.async.commit_group;" ::: "memory");
}

template <int KTOT, int EPI>
__global__ void __launch_bounds__(256, 1) hgemm(
    const __nv_bfloat16* __restrict__ Ahi, const __nv_bfloat16* __restrict__ Alo, long sA,
    const __nv_bfloat16* __restrict__ Bhi, const __nv_bfloat16* __restrict__ Blo, long sB,
    const float* __restrict__ bias,
    __nv_bfloat16* __restrict__ Ohi, __nv_bfloat16* __restrict__ Olo,
    float* __restrict__ mp) {
    extern __shared__ __align__(1024) char smem[];
    uint32_t sb = s2u(smem);
    const int tid = threadIdx.x, lane = tid & 31, wid = tid >> 5;
    const int nT = blockIdx.x, mT = blockIdx.y, b = blockIdx.z;
    const int mBase = mT * 128, nBase = nT * 128;
    const int m0 = (wid & 3) * 32, n0w = (wid >> 2) * 64;

    // gmem base pointers for this thread's cp.async slice
    const int lrow = tid >> 3, lseg = tid & 7;
    const size_t loff = (size_t)lrow * KTOT + lseg * 8;
    const __nv_bfloat16* pAh = Ahi + (size_t)b * sA + (size_t)mBase * KTOT + loff;
    const __nv_bfloat16* pAl = Alo + (size_t)b * sA + (size_t)mBase * KTOT + loff;
    const __nv_bfloat16* pBh = Bhi + (size_t)b * sB + (size_t)nBase * KTOT + loff;
    const __nv_bfloat16* pBl = Blo + (size_t)b * sB + (size_t)nBase * KTOT + loff;
    const uint32_t sdst0 = sb + lrow * 128 + ((lseg ^ (lrow & 7)) << 4);

    constexpr int NCH = KTOT / 64;
    issue_chunk(sdst0 + 0 * BUFSZ, pAh, pAl, pBh, pBl, KTOT);
    issue_chunk(sdst0 + 1 * BUFSZ, pAh + 64, pAl + 64, pBh + 64, pBl + 64, KTOT);

    float acc[2][8][4] = {};

    // per-lane ldmatrix address components
    const int arow0 = m0 + (lane & 15);
    const uint32_t aoff0 = (uint32_t)arow0 * 128;
    const int ax = arow0 & 7, kb = lane >> 4;
    const int grp = lane >> 3;
    const int brow0 = n0w + (lane & 7) + ((grp & 2) << 2);
    const uint32_t boff0 = (uint32_t)brow0 * 128;
    const int bx = brow0 & 7, kgb = grp & 1;

    for (int c = 0; c < NCH; c++) {
        if (c + 2 < NCH)
            issue_chunk(sdst0 + ((c + 2) % 3) * BUFSZ,
                        pAh + (c + 2) * 64, pAl + (c + 2) * 64,
                        pBh + (c + 2) * 64, pBl + (c + 2) * 64, KTOT);
        if (c + 2 < NCH)      asm volatile("cp.async.wait_group 2;" ::: "memory");
        else if (c + 1 < NCH) asm volatile("cp.async.wait_group 1;" ::: "memory");
        else                  asm volatile("cp.async.wait_group 0;" ::: "memory");
        __syncthreads();

        uint32_t s0 = sb + (c % 3) * BUFSZ;
#pragma unroll
        for (int ks = 0; ks < 4; ks++) {
            uint32_t ah[2][4], al[2][4];
#pragma unroll
            for (int mt = 0; mt < 2; mt++) {
                uint32_t addr = s0 + aoff0 + mt * 2048 + (((((ks << 1) | kb)) ^ ax) << 4);
                ldsm4(addr, ah[mt]);
                ldsm4(addr + PLANE, al[mt]);
            }
#pragma unroll
            for (int np = 0; np < 4; np++) {
                uint32_t bh[4], bl[4];
                uint32_t baddr = s0 + 2 * PLANE + boff0 + np * 2048 +
                                 (((((ks << 1) | kgb)) ^ bx) << 4);
                ldsm4(baddr, bh);
                ldsm4(baddr + PLANE, bl);
#pragma unroll
                for (int mt = 0; mt < 2; mt++) {
#pragma unroll
                    for (int j = 0; j < 2; j++) {
                        float* d = acc[mt][np * 2 + j];
                        mma16816(d, ah[mt], bh + 2 * j);
                        mma16816(d, ah[mt], bl + 2 * j);
                        mma16816(d, al[mt], bh + 2 * j);
                    }
                }
            }
        }
        __syncthreads();
    }

    // accum -> padded fp32 smem
    float* fsm = (float*)smem;
    {
        const int r0 = lane >> 2, c0 = (lane & 3) * 2;
#pragma unroll
        for (int mt = 0; mt < 2; mt++)
#pragma unroll
            for (int nt = 0; nt < 8; nt++) {
                int rr = m0 + mt * 16 + r0;
                int cc = n0w + nt * 8 + c0;
                fsm[rr * PADW + cc]           = acc[mt][nt][0];
                fsm[rr * PADW + cc + 1]       = acc[mt][nt][1];
                fsm[(rr + 8) * PADW + cc]     = acc[mt][nt][2];
                fsm[(rr + 8) * PADW + cc + 1] = acc[mt][nt][3];
            }
    }
    __syncthreads();

    if constexpr (EPI == 0) {
        // relu + hi/lo row-major out
        const int row = tid >> 1, nh = (tid & 1) * 64;
        const float* src = fsm + row * PADW + nh;
        size_t go = ((size_t)(b * N_ + mBase + row)) * H_ + nBase + nh;
#pragma unroll
        for (int q = 0; q < 8; q++) {
            uint32_t hp[4], lp[4];
#pragma unroll
            for (int j = 0; j < 4; j++) {
                float v0 = fmaxf(src[q * 8 + j * 2], 0.0f);
                float v1 = fmaxf(src[q * 8 + j * 2 + 1], 0.0f);
                __nv_bfloat16 h0, l0, h1, l1;
                split_bf(v0, h0, l0); split_bf(v1, h1, l1);
                hp[j] = pack2(h0, h1); lp[j] = pack2(l0, l1);
            }
            *(uint4*)(Ohi + go + q * 8) = make_uint4(hp[0], hp[1], hp[2], hp[3]);
            *(uint4*)(Olo + go + q * 8) = make_uint4(lp[0], lp[1], lp[2], lp[3]);
        }
    } else if constexpr (EPI == 1) {
        // bias + hi/lo transposed ([N,K]) out
        const int n = tid >> 1, mh = (tid & 1) * 64;
        const float bv = bias[nBase + n];
        size_t go = ((size_t)(b * H_ + nBase + n)) * N_ + mBase + mh;
#pragma unroll
        for (int q = 0; q < 8; q++) {
            uint32_t hp[4], lp[4];
#pragma unroll
            for (int j = 0; j < 4; j++) {
                float v0 = fsm[(mh + q * 8 + j * 2) * PADW + n] + bv;
                float v1 = fsm[(mh + q * 8 + j * 2 + 1) * PADW + n] + bv;
                __nv_bfloat16 h0, l0, h1, l1;
                split_bf(v0, h0, l0); split_bf(v1, h1, l1);
                hp[j] = pack2(h0, h1); lp[j] = pack2(l0, l1);
            }
            *(uint4*)(Ohi + go + q * 8) = make_uint4(hp[0], hp[1], hp[2], hp[3]);
            *(uint4*)(Olo + go + q * 8) = make_uint4(lp[0], lp[1], lp[2], lp[3]);
        }
    } else {
        // relu + partial column sums (mean path)
        const int col = tid & 127, half = tid >> 7;
        float s = 0.0f;
#pragma unroll 16
        for (int r = 0; r < 64; r++)
            s += fmaxf(fsm[(half * 64 + r) * PADW + col], 0.0f);
        float* red = fsm + 128 * PADW;
        red[tid] = s;
        __syncthreads();
        if (tid < 128)
            mp[((size_t)mT * B_ + b) * H_ + nBase + tid] = red[tid] + red[tid + 128];
    }
}

// ---------------------------------------------------------------------------
// XW1^T = (node_emb @ w1 + b1)^T as bf16 hi/lo  (tiny, batch-invariant)
// ---------------------------------------------------------------------------
__global__ void xw1_kernel(const float* __restrict__ X, const float* __restrict__ w1,
                           const float* __restrict__ b1) {
    int i = blockIdx.x;   // node
    int h = threadIdx.x;  // hidden
    __shared__ float xr[F_];
    if (h < F_) xr[h] = X[i * F_ + h];
    __syncthreads();
    float acc = b1[h];
#pragma unroll 8
    for (int k = 0; k < F_; k++) acc = fmaf(xr[k], w1[k * H_ + h], acc);
    __nv_bfloat16 hi, lo;
    split_bf(acc, hi, lo);
    g_XW1thi[h * N_ + i] = hi;
    g_XW1tlo[h * N_ + i] = lo;
}

// ---------------------------------------------------------------------------
// w^T as bf16 hi/lo (512x512, smem transpose)
// ---------------------------------------------------------------------------
__global__ void wtrans_kernel(const float* __restrict__ w,
                              __nv_bfloat16* __restrict__ thi,
                              __nv_bfloat16* __restrict__ tlo) {
    __shared__ float t[32][33];
    int n0 = blockIdx.x * 32, k0 = blockIdx.y * 32;
    t[threadIdx.y][threadIdx.x] = w[(k0 + threadIdx.y) * H_ + n0 + threadIdx.x];
    __syncthreads();
    float v = t[threadIdx.x][threadIdx.y];  // w[k0+tx][n0+ty]
    __nv_bfloat16 hi, lo;
    split_bf(v, hi, lo);
    thi[(n0 + threadIdx.y) * H_ + k0 + threadIdx.x] = hi;
    tlo[(n0 + threadIdx.y) * H_ + k0 + threadIdx.x] = lo;
}

// ---------------------------------------------------------------------------
// d_inv_sqrt per (batch, node)
// ---------------------------------------------------------------------------
__global__ void dinv_kernel(const float* __restrict__ z) {
    int b = blockIdx.x;
    int t = threadIdx.x;
    __shared__ float tile[32][N_];
    __shared__ float rs[N_];
    const float* Z = z + (size_t)b * N_ * N_;
    float cs = 0.0f;
    for (int j0 = 0; j0 < N_; j0 += 32) {
#pragma unroll
        for (int r = 0; r < 32; r++) {
            float v = sigmoidf_(Z[(j0 + r) * N_ + t]);
            tile[r][t] = v;
            cs += v;
        }
        __syncthreads();
        int warp = t >> 5, lane = t & 31;
#pragma unroll
        for (int rr = 0; rr < 4; rr++) {
            int r = warp * 4 + rr;
            float s = 0.0f;
#pragma unroll
            for (int c = 0; c < 8; c++) s += tile[r][lane + 32 * c];
#pragma unroll
            for (int o = 16; o; o >>= 1) s += __shfl_down_sync(0xffffffffu, s, o);
            if (lane == 0) rs[j0 + r] = s;
        }
        __syncthreads();
    }
    float D = 1.0f + 0.5f * (rs[t] + cs) + 1e-6f;
    g_dinv[b * N_ + t] = rsqrtf(D);
}

// ---------------------------------------------------------------------------
// normA as bf16 hi/lo planes
// ---------------------------------------------------------------------------
__global__ void norma_kernel(const float* __restrict__ z) {
    int b = blockIdx.z;
    int i0 = blockIdx.y * 32, j0 = blockIdx.x * 32;
    int tx = threadIdx.x, ty = threadIdx.y;
    __shared__ float tT[32][33];
    const float* Z = z + (size_t)b * N_ * N_;
    tT[ty][tx] = Z[(j0 + ty) * N_ + i0 + tx];
    __syncthreads();
    int i = i0 + ty, j = j0 + tx;
    float a = sigmoidf_(Z[i * N_ + j]);
    float at = sigmoidf_(tT[tx][ty]);
    float v = 0.5f * (a + at);
    if (i == j) v += 1.0f;
    v *= g_dinv[b * N_ + i] * g_dinv[b * N_ + j];
    __nv_bfloat16 hi, lo;
    split_bf(v, hi, lo);
    size_t o = (size_t)b * N_ * N_ + i * N_ + j;
    g_nAhi[o] = hi;
    g_nAlo[o] = lo;
}

// ---------------------------------------------------------------------------
// logits from meanpart
// ---------------------------------------------------------------------------
__global__ void readout_kernel(const float* __restrict__ fcw, const float* __restrict__ fcb,
                               float* __restrict__ out) {
    int b = blockIdx.x;
    int h = threadIdx.x;
    float ge = (g_meanpart[b * H_ + h] + g_meanpart[B_ * H_ + b * H_ + h]) * (1.0f / N_);
    __shared__ float s0[H_], s1[H_];
    s0[h] = ge * fcw[h * 2 + 0];
    s1[h] = ge * fcw[h * 2 + 1];
    __syncthreads();
    for (int st = 256; st > 0; st >>= 1) {
        if (h < st) { s0[h] += s0[h + st]; s1[h] += s1[h + st]; }
        __syncthreads();
    }
    if (h == 0) {
        out[b * 2 + 0] = s0[0] + fcb[0];
        out[b * 2 + 1] = s1[0] + fcb[1];
    }
}

// ---------------------------------------------------------------------------
extern "C" void kernel_launch(void* const* d_in, const int* in_sizes, int n_in,
                              void* d_out, int out_size) {
    const float* z   = (const float*)d_in[0];
    const float* ne  = (const float*)d_in[1];
    const float* w1  = (const float*)d_in[2];
    const float* b1  = (const float*)d_in[3];
    const float* w2  = (const float*)d_in[4];
    const float* b2  = (const float*)d_in[5];
    const float* w3  = (const float*)d_in[6];
    const float* b3  = (const float*)d_in[7];
    const float* fcw = (const float*)d_in[8];
    const float* fcb = (const float*)d_in[9];
    float* out = (float*)d_out;

    __nv_bfloat16 *pnAhi, *pnAlo, *pHhi, *pHlo, *pYthi, *pYtlo;
    __nv_bfloat16 *pXW1thi, *pXW1tlo, *pw2thi, *pw2tlo, *pw3thi, *pw3tlo;
    float* pmean;
    cudaGetSymbolAddress((void**)&pnAhi, g_nAhi);
    cudaGetSymbolAddress((void**)&pnAlo, g_nAlo);
    cudaGetSymbolAddress((void**)&pHhi, g_Hhi);
    cudaGetSymbolAddress((void**)&pHlo, g_Hlo);
    cudaGetSymbolAddress((void**)&pYthi, g_Ythi);
    cudaGetSymbolAddress((void**)&pYtlo, g_Ytlo);
    cudaGetSymbolAddress((void**)&pXW1thi, g_XW1thi);
    cudaGetSymbolAddress((void**)&pXW1tlo, g_XW1tlo);
    cudaGetSymbolAddress((void**)&pw2thi, g_w2thi);
    cudaGetSymbolAddress((void**)&pw2tlo, g_w2tlo);
    cudaGetSymbolAddress((void**)&pw3thi, g_w3thi);
    cudaGetSymbolAddress((void**)&pw3tlo, g_w3tlo);
    cudaGetSymbolAddress((void**)&pmean, g_meanpart);

    cudaFuncSetAttribute(hgemm<256, 0>, cudaFuncAttributeMaxDynamicSharedMemorySize, SMEM_G);
    cudaFuncSetAttribute(hgemm<512, 1>, cudaFuncAttributeMaxDynamicSharedMemorySize, SMEM_G);
    cudaFuncSetAttribute(hgemm<256, 2>, cudaFuncAttributeMaxDynamicSharedMemorySize, SMEM_G);

    xw1_kernel<<<N_, H_>>>(ne, w1, b1);
    wtrans_kernel<<<dim3(16, 16), dim3(32, 32)>>>(w2, pw2thi, pw2tlo);
    wtrans_kernel<<<dim3(16, 16), dim3(32, 32)>>>(w3, pw3thi, pw3tlo);
    dinv_kernel<<<B_, N_>>>(z);
    norma_kernel<<<dim3(8, 8, B_), dim3(32, 32)>>>(z);

    dim3 gg(4, 2, B_);
    // H1 = relu(normA @ XW1)
    hgemm<256, 0><<<gg, 256, SMEM_G>>>(pnAhi, pnAlo, (long)N_ * N_,
                                       pXW1thi, pXW1tlo, 0, nullptr,
                                       pHhi, pHlo, nullptr);
    // Y2^T = (H1 @ w2 + b2)^T
    hgemm<512, 1><<<gg, 256, SMEM_G>>>(pHhi, pHlo, (long)N_ * H_,
                                       pw2thi, pw2tlo, 0, b2,
                                       pYthi, pYtlo, nullptr);
    // H2 = relu(normA @ Y2)
    hgemm<256, 0><<<gg, 256, SMEM_G>>>(pnAhi, pnAlo, (long)N_ * N_,
                                       pYthi, pYtlo, (long)H_ * N_, nullptr,
                                       pHhi, pHlo, nullptr);
    // Y3^T = (H2 @ w3 + b3)^T
    hgemm<512, 1><<<gg, 256, SMEM_G>>>(pHhi, pHlo, (long)N_ * H_,
                                       pw3thi, pw3tlo, 0, b3,
                                       pYthi, pYtlo, nullptr);
    // meanpart = colsum(relu(normA @ Y3)) per m-tile
    hgemm<256, 2><<<gg, 256, SMEM_G>>>(pnAhi, pnAlo, (long)N_ * N_,
                                       pYthi, pYtlo, (long)H_ * N_, nullptr,
                                       nullptr, nullptr, pmean);

    readout_kernel<<<B_, H_>>>(fcw, fcb, out);
}

// round 4
// speedup vs baseline: 2.3727x; 1.0587x over previous
#include <cuda_runtime.h>
#include <cuda_bf16.h>
#include <cstdint>
#include <cstring>

#define B_ 256
#define N_ 256
#define F_ 64
#define H_ 512

// ---------------------------------------------------------------------------
// Scratch (static device globals — allocation-free per harness rules)
// ---------------------------------------------------------------------------
__device__ __align__(16) __nv_bfloat16 g_nAhi[(size_t)B_ * N_ * N_];
__device__ __align__(16) __nv_bfloat16 g_nAlo[(size_t)B_ * N_ * N_];
__device__ __align__(16) __nv_bfloat16 g_Hhi[(size_t)B_ * N_ * H_];
__device__ __align__(16) __nv_bfloat16 g_Hlo[(size_t)B_ * N_ * H_];
__device__ __align__(16) __nv_bfloat16 g_Ythi[(size_t)B_ * H_ * N_];
__device__ __align__(16) __nv_bfloat16 g_Ytlo[(size_t)B_ * H_ * N_];
__device__ __align__(16) __nv_bfloat16 g_XW1thi[H_ * N_];
__device__ __align__(16) __nv_bfloat16 g_XW1tlo[H_ * N_];
__device__ __align__(16) __nv_bfloat16 g_w2thi[H_ * H_];
__device__ __align__(16) __nv_bfloat16 g_w2tlo[H_ * H_];
__device__ __align__(16) __nv_bfloat16 g_w3thi[H_ * H_];
__device__ __align__(16) __nv_bfloat16 g_w3tlo[H_ * H_];
__device__ float g_rowsum[B_ * N_];
__device__ float g_colsum[B_ * N_];
__device__ float g_dinv[B_ * N_];
__device__ float g_meanpart[2 * B_ * H_];

// ---------------------------------------------------------------------------
// Helpers (portable PTX only — no tcgen05 under this toolchain)
// ---------------------------------------------------------------------------
__device__ __forceinline__ uint32_t s2u(const void* p) {
    uint32_t a;
    asm("{ .reg .u64 t; cvta.to.shared.u64 t, %1; cvt.u32.u64 %0, t; }" : "=r"(a) : "l"(p));
    return a;
}
__device__ __forceinline__ void cpasync16(uint32_t dst, const void* src) {
    asm volatile("cp.async.cg.shared.global [%0], [%1], 16;" :: "r"(dst), "l"(src));
}
__device__ __forceinline__ void ldsm4(uint32_t addr, uint32_t* r) {
    asm volatile("ldmatrix.sync.aligned.m8n8.x4.shared.b16 {%0,%1,%2,%3}, [%4];"
                 : "=r"(r[0]), "=r"(r[1]), "=r"(r[2]), "=r"(r[3]) : "r"(addr));
}
__device__ __forceinline__ void mma16816(float* d, const uint32_t* a, const uint32_t* b) {
    asm volatile(
        "mma.sync.aligned.m16n8k16.row.col.f32.bf16.bf16.f32 "
        "{%0,%1,%2,%3}, {%4,%5,%6,%7}, {%8,%9}, {%0,%1,%2,%3};"
        : "+f"(d[0]), "+f"(d[1]), "+f"(d[2]), "+f"(d[3])
        : "r"(a[0]), "r"(a[1]), "r"(a[2]), "r"(a[3]), "r"(b[0]), "r"(b[1]));
}
__device__ __forceinline__ uint32_t pack2(__nv_bfloat16 a, __nv_bfloat16 b) {
    unsigned short ua, ub;
    memcpy(&ua, &a, 2); memcpy(&ub, &b, 2);
    return (uint32_t)ua | ((uint32_t)ub << 16);
}
__device__ __forceinline__ void split_bf(float v, __nv_bfloat16& h, __nv_bfloat16& l) {
    h = __float2bfloat16(v);
    l = __float2bfloat16(v - __bfloat162float(h));
}
__device__ __forceinline__ float sigmoidf_(float x) { return 1.0f / (1.0f + expf(-x)); }

// ---------------------------------------------------------------------------
// HMMA GEMM: 128(M) x 256(N) CTA tile, 512 threads (16 warps of 32x64),
// K via 64-wide chunks, 2-stage cp.async pipeline.
// A row-major [M,KTOT]; B pre-transposed [N,KTOT].
// Smem/stage: Ahi 16K | Alo 16K | Bhi 32K | Blo 32K = 96KB; 2 stages = 192KB.
// EPI: 0 = relu + hi/lo row-major out; 1 = bias + hi/lo transposed out;
//      2 = relu + column-sum partial reduce (mean path)
// ---------------------------------------------------------------------------
constexpr int APLANE = 16384;
constexpr int BPLANE = 32768;
constexpr int STAGE = 2 * APLANE + 2 * BPLANE;   // 98304
constexpr int SMEM_G = 2 * STAGE;                // 196608
constexpr int PADW = 257;

__device__ __forceinline__ void issue_chunk(uint32_t sbase, int tid,
                                            const __nv_bfloat16* ah, const __nv_bfloat16* al,
                                            const __nv_bfloat16* bh, const __nv_bfloat16* bl,
                                            int ldk) {
    // A planes: 128 rows x 8 segs = 1024 chunks of 16B; 2 per thread per plane
#pragma unroll
    for (int i = 0; i < 2; i++) {
        int idx = tid + i * 512;
        int row = idx >> 3, seg = idx & 7;
        size_t go = (size_t)row * ldk + seg * 8;
        uint32_t sw = (uint32_t)(row * 128) + (uint32_t)((seg ^ (row & 7)) << 4);
        cpasync16(sbase + sw, ah + go);
        cpasync16(sbase + APLANE + sw, al + go);
    }
    // B planes: 256 rows x 8 segs = 2048 chunks; 4 per thread per plane
#pragma unroll
    for (int i = 0; i < 4; i++) {
        int idx = tid + i * 512;
        int row = idx >> 3, seg = idx & 7;
        size_t go = (size_t)row * ldk + seg * 8;
        uint32_t sw = (uint32_t)(row * 128) + (uint32_t)((seg ^ (row & 7)) << 4);
        cpasync16(sbase + 2 * APLANE + sw, bh + go);
        cpasync16(sbase + 2 * APLANE + BPLANE + sw, bl + go);
    }
    asm volatile("cp.async.commit_group;" ::: "memory");
}

template <int KTOT, int EPI>
__global__ void __launch_bounds__(512, 1) hgemm(
    const __nv_bfloat16* __restrict__ Ahi, const __nv_bfloat16* __restrict__ Alo, long sA,
    const __nv_bfloat16* __restrict__ Bhi, const __nv_bfloat16* __restrict__ Blo, long sB,
    const float* __restrict__ bias,
    __nv_bfloat16* __restrict__ Ohi, __nv_bfloat16* __restrict__ Olo,
    float* __restrict__ mp) {
    extern __shared__ __align__(1024) char smem[];
    uint32_t sb = s2u(smem);
    const int tid = threadIdx.x, lane = tid & 31, wid = tid >> 5;
    const int nT = blockIdx.x, mT = blockIdx.y, b = blockIdx.z;
    const int mBase = mT * 128, nBase = nT * 256;
    const int m0 = (wid & 3) * 32, n0w = (wid >> 2) * 64;

    const __nv_bfloat16* pAh = Ahi + (size_t)b * sA + (size_t)mBase * KTOT;
    const __nv_bfloat16* pAl = Alo + (size_t)b * sA + (size_t)mBase * KTOT;
    const __nv_bfloat16* pBh = Bhi + (size_t)b * sB + (size_t)nBase * KTOT;
    const __nv_bfloat16* pBl = Blo + (size_t)b * sB + (size_t)nBase * KTOT;

    constexpr int NCH = KTOT / 64;
    issue_chunk(sb, tid, pAh, pAl, pBh, pBl, KTOT);
    issue_chunk(sb + STAGE, tid, pAh + 64, pAl + 64, pBh + 64, pBl + 64, KTOT);

    float acc[2][8][4] = {};

    const int arow0 = m0 + (lane & 15);
    const uint32_t aoff0 = (uint32_t)arow0 * 128;
    const int ax = arow0 & 7, kb = lane >> 4;
    const int grp = lane >> 3;
    const int brow0 = n0w + (lane & 7) + ((grp & 2) << 2);
    const uint32_t boff0 = (uint32_t)brow0 * 128;
    const int bx = brow0 & 7, kgb = grp & 1;

    for (int c = 0; c < NCH; c++) {
        if (c + 1 < NCH) asm volatile("cp.async.wait_group 1;" ::: "memory");
        else             asm volatile("cp.async.wait_group 0;" ::: "memory");
        __syncthreads();

        uint32_t s0 = sb + (c & 1) * STAGE;
#pragma unroll
        for (int ks = 0; ks < 4; ks++) {
            uint32_t ah[2][4], al[2][4];
#pragma unroll
            for (int mt = 0; mt < 2; mt++) {
                uint32_t addr = s0 + aoff0 + mt * 2048 + (((((ks << 1) | kb)) ^ ax) << 4);
                ldsm4(addr, ah[mt]);
                ldsm4(addr + APLANE, al[mt]);
            }
#pragma unroll
            for (int np = 0; np < 4; np++) {
                uint32_t bh[4], bl[4];
                uint32_t baddr = s0 + 2 * APLANE + boff0 + np * 2048 +
                                 (((((ks << 1) | kgb)) ^ bx) << 4);
                ldsm4(baddr, bh);
                ldsm4(baddr + BPLANE, bl);
#pragma unroll
                for (int mt = 0; mt < 2; mt++) {
#pragma unroll
                    for (int j = 0; j < 2; j++) {
                        float* d = acc[mt][np * 2 + j];
                        mma16816(d, ah[mt], bh + 2 * j);
                        mma16816(d, ah[mt], bl + 2 * j);
                        mma16816(d, al[mt], bh + 2 * j);
                    }
                }
            }
        }
        __syncthreads();
        if (c + 2 < NCH)
            issue_chunk(sb + (c & 1) * STAGE, tid,
                        pAh + (c + 2) * 64, pAl + (c + 2) * 64,
                        pBh + (c + 2) * 64, pBl + (c + 2) * 64, KTOT);
    }

    // accum -> padded fp32 smem (128 x 256, stride PADW)
    float* fsm = (float*)smem;
    {
        const int r0 = lane >> 2, c0 = (lane & 3) * 2;
#pragma unroll
        for (int mt = 0; mt < 2; mt++)
#pragma unroll
            for (int nt = 0; nt < 8; nt++) {
                int rr = m0 + mt * 16 + r0;
                int cc = n0w + nt * 8 + c0;
                fsm[rr * PADW + cc]           = acc[mt][nt][0];
                fsm[rr * PADW + cc + 1]       = acc[mt][nt][1];
                fsm[(rr + 8) * PADW + cc]     = acc[mt][nt][2];
                fsm[(rr + 8) * PADW + cc + 1] = acc[mt][nt][3];
            }
    }
    __syncthreads();

    if constexpr (EPI == 0) {
        // relu + hi/lo row-major out
        const int row = tid >> 2, q4 = (tid & 3) * 64;
        const float* src = fsm + row * PADW + q4;
        size_t go = ((size_t)(b * N_ + mBase + row)) * H_ + nBase + q4;
#pragma unroll
        for (int q = 0; q < 8; q++) {
            uint32_t hp[4], lp[4];
#pragma unroll
            for (int j = 0; j < 4; j++) {
                float v0 = fmaxf(src[q * 8 + j * 2], 0.0f);
                float v1 = fmaxf(src[q * 8 + j * 2 + 1], 0.0f);
                __nv_bfloat16 h0, l0, h1, l1;
                split_bf(v0, h0, l0); split_bf(v1, h1, l1);
                hp[j] = pack2(h0, h1); lp[j] = pack2(l0, l1);
            }
            *(uint4*)(Ohi + go + q * 8) = make_uint4(hp[0], hp[1], hp[2], hp[3]);
            *(uint4*)(Olo + go + q * 8) = make_uint4(lp[0], lp[1], lp[2], lp[3]);
        }
    } else if constexpr (EPI == 1) {
        // bias + hi/lo transposed ([N,K]) out
        const int n = tid >> 1, mh = (tid & 1) * 64;
        const float bv = bias[nBase + n];
        size_t go = ((size_t)(b * H_ + nBase + n)) * N_ + mBase + mh;
#pragma unroll
        for (int q = 0; q < 8; q++) {
            uint32_t hp[4], lp[4];
#pragma unroll
            for (int j = 0; j < 4; j++) {
                float v0 = fsm[(mh + q * 8 + j * 2) * PADW + n] + bv;
                float v1 = fsm[(mh + q * 8 + j * 2 + 1) * PADW + n] + bv;
                __nv_bfloat16 h0, l0, h1, l1;
                split_bf(v0, h0, l0); split_bf(v1, h1, l1);
                hp[j] = pack2(h0, h1); lp[j] = pack2(l0, l1);
            }
            *(uint4*)(Ohi + go + q * 8) = make_uint4(hp[0], hp[1], hp[2], hp[3]);
            *(uint4*)(Olo + go + q * 8) = make_uint4(lp[0], lp[1], lp[2], lp[3]);
        }
    } else {
        // relu + partial column sums (mean path)
        const int col = tid & 255, half = tid >> 8;
        float s = 0.0f;
#pragma unroll 16
        for (int r = 0; r < 64; r++)
            s += fmaxf(fsm[(half * 64 + r) * PADW + col], 0.0f);
        float* red = fsm + 128 * PADW;
        red[half * 256 + col] = s;
        __syncthreads();
        if (tid < 256)
            mp[((size_t)mT * B_ + b) * H_ + nBase + tid] = red[tid] + red[tid + 256];
    }
}

// ---------------------------------------------------------------------------
// rowsum[b][i] = sum_j sigmoid(z[b,i,j])  — grid (B_, 8), 256 threads
// ---------------------------------------------------------------------------
__global__ void rowsum_kernel(const float* __restrict__ z) {
    int b = blockIdx.x, strip = blockIdx.y;
    int lane = threadIdx.x & 31, w = threadIdx.x >> 5;
    const float* Z = z + (size_t)b * N_ * N_;
#pragma unroll
    for (int rr = 0; rr < 4; rr++) {
        int row = strip * 32 + w * 4 + rr;
        const float* R = Z + (size_t)row * N_;
        float s = 0.0f;
#pragma unroll
        for (int c = 0; c < 8; c++) s += sigmoidf_(R[lane + 32 * c]);
#pragma unroll
        for (int o = 16; o; o >>= 1) s += __shfl_down_sync(0xffffffffu, s, o);
        if (lane == 0) g_rowsum[b * N_ + row] = s;
    }
}

// ---------------------------------------------------------------------------
// colsum[b][j] = sum_i sigmoid(z[b,i,j])  — grid (B_, 8), 256 threads
// warp w covers rows [w*32, w*32+32), cols chunk*32 + lane
// ---------------------------------------------------------------------------
__global__ void colsum_kernel(const float* __restrict__ z) {
    int b = blockIdx.x, chunk = blockIdx.y;
    int lane = threadIdx.x & 31, w = threadIdx.x >> 5;
    int col = chunk * 32 + lane;
    const float* Z = z + (size_t)b * N_ * N_;
    float s = 0.0f;
#pragma unroll 8
    for (int r = 0; r < 32; r++)
        s += sigmoidf_(Z[(size_t)(w * 32 + r) * N_ + col]);
    __shared__ float red[8][32];
    red[w][lane] = s;
    __syncthreads();
    if (w == 0) {
        float t = red[0][lane];
#pragma unroll
        for (int k = 1; k < 8; k++) t += red[k][lane];
        g_colsum[b * N_ + col] = t;
    }
}

__global__ void dinv_combine_kernel() {
    int i = blockIdx.x * 256 + threadIdx.x;
    float D = 1.0f + 0.5f * (g_rowsum[i] + g_colsum[i]) + 1e-6f;
    g_dinv[i] = rsqrtf(D);
}

// ---------------------------------------------------------------------------
// normA symmetric tile-pair kernel: z read once.
// grid (36 upper-tri block pairs, B_), block 32x32.
// ---------------------------------------------------------------------------
__global__ void norma_kernel(const float* __restrict__ z) {
    int p = blockIdx.x, b = blockIdx.y;
    int bi = 0, rem = p;
    while (rem >= 8 - bi) { rem -= 8 - bi; bi++; }
    int bj = bi + rem;
    int i0 = bi * 32, j0 = bj * 32;
    int tx = threadIdx.x, ty = threadIdx.y;
    __shared__ float tA[32][33];   // sig(z[I,J])
    __shared__ float tB[32][33];   // sig(z[J,I])
    const float* Z = z + (size_t)b * N_ * N_;
    tA[ty][tx] = sigmoidf_(Z[(size_t)(i0 + ty) * N_ + j0 + tx]);
    if (bi != bj) tB[ty][tx] = sigmoidf_(Z[(size_t)(j0 + ty) * N_ + i0 + tx]);
    __syncthreads();
    const float di = g_dinv[b * N_ + i0 + ty];
    const float djA = g_dinv[b * N_ + j0 + tx];
    // tile (I,J)
    {
        float zt = (bi == bj) ? tA[tx][ty] : tB[tx][ty];
        float v = 0.5f * (tA[ty][tx] + zt);
        if (i0 + ty == j0 + tx) v += 1.0f;
        v *= di * djA;
        __nv_bfloat16 h, l; split_bf(v, h, l);
        size_t o = (size_t)b * N_ * N_ + (size_t)(i0 + ty) * N_ + j0 + tx;
        g_nAhi[o] = h; g_nAlo[o] = l;
    }
    if (bi != bj) {
        const float di2 = g_dinv[b * N_ + j0 + ty];
        const float dj2 = g_dinv[b * N_ + i0 + tx];
        float v = 0.5f * (tB[ty][tx] + tA[tx][ty]);
        v *= di2 * dj2;
        __nv_bfloat16 h, l; split_bf(v, h, l);
        size_t o = (size_t)b * N_ * N_ + (size_t)(j0 + ty) * N_ + i0 + tx;
        g_nAhi[o] = h; g_nAlo[o] = l;
    }
}

// ---------------------------------------------------------------------------
// XW1^T = (node_emb @ w1 + b1)^T as bf16 hi/lo  (tiny, batch-invariant)
// ---------------------------------------------------------------------------
__global__ void xw1_kernel(const float* __restrict__ X, const float* __restrict__ w1,
                           const float* __restrict__ b1) {
    int i = blockIdx.x;
    int h = threadIdx.x;
    __shared__ float xr[F_];
    if (h < F_) xr[h] = X[i * F_ + h];
    __syncthreads();
    float acc = b1[h];
#pragma unroll 8
    for (int k = 0; k < F_; k++) acc = fmaf(xr[k], w1[k * H_ + h], acc);
    __nv_bfloat16 hi, lo;
    split_bf(acc, hi, lo);
    g_XW1thi[h * N_ + i] = hi;
    g_XW1tlo[h * N_ + i] = lo;
}

// ---------------------------------------------------------------------------
// w^T as bf16 hi/lo (512x512, smem transpose)
// ---------------------------------------------------------------------------
__global__ void wtrans_kernel(const float* __restrict__ w,
                              __nv_bfloat16* __restrict__ thi,
                              __nv_bfloat16* __restrict__ tlo) {
    __shared__ float t[32][33];
    int n0 = blockIdx.x * 32, k0 = blockIdx.y * 32;
    t[threadIdx.y][threadIdx.x] = w[(k0 + threadIdx.y) * H_ + n0 + threadIdx.x];
    __syncthreads();
    float v = t[threadIdx.x][threadIdx.y];
    __nv_bfloat16 hi, lo;
    split_bf(v, hi, lo);
    thi[(n0 + threadIdx.y) * H_ + k0 + threadIdx.x] = hi;
    tlo[(n0 + threadIdx.y) * H_ + k0 + threadIdx.x] = lo;
}

// ---------------------------------------------------------------------------
// logits from meanpart
// ---------------------------------------------------------------------------
__global__ void readout_kernel(const float* __restrict__ fcw, const float* __restrict__ fcb,
                               float* __restrict__ out) {
    int b = blockIdx.x;
    int h = threadIdx.x;
    float ge = (g_meanpart[b * H_ + h] + g_meanpart[B_ * H_ + b * H_ + h]) * (1.0f / N_);
    __shared__ float s0[H_], s1[H_];
    s0[h] = ge * fcw[h * 2 + 0];
    s1[h] = ge * fcw[h * 2 + 1];
    __syncthreads();
    for (int st = 256; st > 0; st >>= 1) {
        if (h < st) { s0[h] += s0[h + st]; s1[h] += s1[h + st]; }
        __syncthreads();
    }
    if (h == 0) {
        out[b * 2 + 0] = s0[0] + fcb[0];
        out[b * 2 + 1] = s1[0] + fcb[1];
    }
}

// ---------------------------------------------------------------------------
extern "C" void kernel_launch(void* const* d_in, const int* in_sizes, int n_in,
                              void* d_out, int out_size) {
    const float* z   = (const float*)d_in[0];
    const float* ne  = (const float*)d_in[1];
    const float* w1  = (const float*)d_in[2];
    const float* b1  = (const float*)d_in[3];
    const float* w2  = (const float*)d_in[4];
    const float* b2  = (const float*)d_in[5];
    const float* w3  = (const float*)d_in[6];
    const float* b3  = (const float*)d_in[7];
    const float* fcw = (const float*)d_in[8];
    const float* fcb = (const float*)d_in[9];
    float* out = (float*)d_out;

    __nv_bfloat16 *pnAhi, *pnAlo, *pHhi, *pHlo, *pYthi, *pYtlo;
    __nv_bfloat16 *pXW1thi, *pXW1tlo, *pw2thi, *pw2tlo, *pw3thi, *pw3tlo;
    float* pmean;
    cudaGetSymbolAddress((void**)&pnAhi, g_nAhi);
    cudaGetSymbolAddress((void**)&pnAlo, g_nAlo);
    cudaGetSymbolAddress((void**)&pHhi, g_Hhi);
    cudaGetSymbolAddress((void**)&pHlo, g_Hlo);
    cudaGetSymbolAddress((void**)&pYthi, g_Ythi);
    cudaGetSymbolAddress((void**)&pYtlo, g_Ytlo);
    cudaGetSymbolAddress((void**)&pXW1thi, g_XW1thi);
    cudaGetSymbolAddress((void**)&pXW1tlo, g_XW1tlo);
    cudaGetSymbolAddress((void**)&pw2thi, g_w2thi);
    cudaGetSymbolAddress((void**)&pw2tlo, g_w2tlo);
    cudaGetSymbolAddress((void**)&pw3thi, g_w3thi);
    cudaGetSymbolAddress((void**)&pw3tlo, g_w3tlo);
    cudaGetSymbolAddress((void**)&pmean, g_meanpart);

    cudaFuncSetAttribute(hgemm<256, 0>, cudaFuncAttributeMaxDynamicSharedMemorySize, SMEM_G);
    cudaFuncSetAttribute(hgemm<512, 1>, cudaFuncAttributeMaxDynamicSharedMemorySize, SMEM_G);
    cudaFuncSetAttribute(hgemm<256, 2>, cudaFuncAttributeMaxDynamicSharedMemorySize, SMEM_G);

    xw1_kernel<<<N_, H_>>>(ne, w1, b1);
    wtrans_kernel<<<dim3(16, 16), dim3(32, 32)>>>(w2, pw2thi, pw2tlo);
    wtrans_kernel<<<dim3(16, 16), dim3(32, 32)>>>(w3, pw3thi, pw3tlo);
    rowsum_kernel<<<dim3(B_, 8), 256>>>(z);
    colsum_kernel<<<dim3(B_, 8), 256>>>(z);
    dinv_combine_kernel<<<B_, 256>>>();
    norma_kernel<<<dim3(36, B_), dim3(32, 32)>>>(z);

    dim3 gg(2, 2, B_);   // nT (256-wide), mT (128-tall), batch
    // H1 = relu(normA @ XW1)
    hgemm<256, 0><<<gg, 512, SMEM_G>>>(pnAhi, pnAlo, (long)N_ * N_,
                                       pXW1thi, pXW1tlo, 0, nullptr,
                                       pHhi, pHlo, nullptr);
    // Y2^T = (H1 @ w2 + b2)^T
    hgemm<512, 1><<<gg, 512, SMEM_G>>>(pHhi, pHlo, (long)N_ * H_,
                                       pw2thi, pw2tlo, 0, b2,
                                       pYthi, pYtlo, nullptr);
    // H2 = relu(normA @ Y2)
    hgemm<256, 0><<<gg, 512, SMEM_G>>>(pnAhi, pnAlo, (long)N_ * N_,
                                       pYthi, pYtlo, (long)H_ * N_, nullptr,
                                       pHhi, pHlo, nullptr);
    // Y3^T = (H2 @ w3 + b3)^T
    hgemm<512, 1><<<gg, 512, SMEM_G>>>(pHhi, pHlo, (long)N_ * H_,
                                       pw3thi, pw3tlo, 0, b3,
                                       pYthi, pYtlo, nullptr);
    // meanpart = colsum(relu(normA @ Y3)) per m-tile
    hgemm<256, 2><<<gg, 512, SMEM_G>>>(pnAhi, pnAlo, (long)N_ * N_,
                                       pYthi, pYtlo, (long)H_ * N_, nullptr,
                                       nullptr, nullptr, pmean);

    readout_kernel<<<B_, H_>>>(fcw, fcb, out);
}

// round 5
// speedup vs baseline: 2.4479x; 1.0317x over previous
#include <cuda_runtime.h>
#include <cuda_bf16.h>
#include <cstdint>
#include <cstring>

#define B_ 256
#define N_ 256
#define F_ 64
#define H_ 512

// ---------------------------------------------------------------------------
// Scratch (static device globals — allocation-free per harness rules)
// ---------------------------------------------------------------------------
__device__ __align__(16) __nv_bfloat16 g_nAhi[(size_t)B_ * N_ * N_];
__device__ __align__(16) __nv_bfloat16 g_nAlo[(size_t)B_ * N_ * N_];
__device__ __align__(16) __nv_bfloat16 g_Hhi[(size_t)B_ * N_ * H_];
__device__ __align__(16) __nv_bfloat16 g_Hlo[(size_t)B_ * N_ * H_];
__device__ __align__(16) __nv_bfloat16 g_Ythi[(size_t)B_ * H_ * N_];
__device__ __align__(16) __nv_bfloat16 g_Ytlo[(size_t)B_ * H_ * N_];
__device__ __align__(16) __nv_bfloat16 g_XW1thi[H_ * N_];
__device__ __align__(16) __nv_bfloat16 g_XW1tlo[H_ * N_];
__device__ __align__(16) __nv_bfloat16 g_w2thi[H_ * H_];
__device__ __align__(16) __nv_bfloat16 g_w2tlo[H_ * H_];
__device__ __align__(16) __nv_bfloat16 g_w3thi[H_ * H_];
__device__ __align__(16) __nv_bfloat16 g_w3tlo[H_ * H_];
__device__ float g_rowsum[B_ * N_];
__device__ float g_colsum[B_ * N_];
__device__ float g_meanpart[2 * B_ * H_];

// ---------------------------------------------------------------------------
// Helpers (portable PTX only — no tcgen05 under this toolchain)
// ---------------------------------------------------------------------------
__device__ __forceinline__ uint32_t s2u(const void* p) {
    uint32_t a;
    asm("{ .reg .u64 t; cvta.to.shared.u64 t, %1; cvt.u32.u64 %0, t; }" : "=r"(a) : "l"(p));
    return a;
}
__device__ __forceinline__ void cpasync16(uint32_t dst, const void* src) {
    asm volatile("cp.async.cg.shared.global [%0], [%1], 16;" :: "r"(dst), "l"(src));
}
__device__ __forceinline__ void ldsm4(uint32_t addr, uint32_t* r) {
    asm volatile("ldmatrix.sync.aligned.m8n8.x4.shared.b16 {%0,%1,%2,%3}, [%4];"
                 : "=r"(r[0]), "=r"(r[1]), "=r"(r[2]), "=r"(r[3]) : "r"(addr));
}
__device__ __forceinline__ void mma16816(float* d, const uint32_t* a, const uint32_t* b) {
    asm volatile(
        "mma.sync.aligned.m16n8k16.row.col.f32.bf16.bf16.f32 "
        "{%0,%1,%2,%3}, {%4,%5,%6,%7}, {%8,%9}, {%0,%1,%2,%3};"
        : "+f"(d[0]), "+f"(d[1]), "+f"(d[2]), "+f"(d[3])
        : "r"(a[0]), "r"(a[1]), "r"(a[2]), "r"(a[3]), "r"(b[0]), "r"(b[1]));
}
__device__ __forceinline__ uint32_t pack2(__nv_bfloat16 a, __nv_bfloat16 b) {
    unsigned short ua, ub;
    memcpy(&ua, &a, 2); memcpy(&ub, &b, 2);
    return (uint32_t)ua | ((uint32_t)ub << 16);
}
__device__ __forceinline__ void split_bf(float v, __nv_bfloat16& h, __nv_bfloat16& l) {
    h = __float2bfloat16(v);
    l = __float2bfloat16(v - __bfloat162float(h));
}
__device__ __forceinline__ float sigmoidf_(float x) { return 1.0f / (1.0f + expf(-x)); }
__device__ __forceinline__ float dinv_of(int b, int i) {
    return rsqrtf(1.0f + 0.5f * (g_rowsum[b * N_ + i] + g_colsum[b * N_ + i]) + 1e-6f);
}

// ---------------------------------------------------------------------------
// HMMA GEMM: 128(M) x 256(N) CTA tile, 256 threads (8 warps of 64x64),
// K via 64-wide chunks, 2-stage cp.async pipeline, 3-pass bf16 hi/lo.
// A row-major [M,KTOT]; B pre-transposed [N,KTOT].
// Smem/stage: Ahi 16K | Alo 16K | Bhi 32K | Blo 32K = 96KB; 2 stages = 192KB.
// EPI: 0 = relu + hi/lo row-major out; 1 = bias + hi/lo transposed out;
//      2 = relu + column-sum partial reduce (mean path)
// ---------------------------------------------------------------------------
constexpr int APLANE = 16384;
constexpr int BPLANE = 32768;
constexpr int STAGE = 2 * APLANE + 2 * BPLANE;   // 98304
constexpr int SMEM_G = 2 * STAGE;                // 196608
constexpr int PADW = 257;

__device__ __forceinline__ void issue_chunk(uint32_t sbase, int tid,
                                            const __nv_bfloat16* ah, const __nv_bfloat16* al,
                                            const __nv_bfloat16* bh, const __nv_bfloat16* bl,
                                            int ldk) {
    // A planes: 128 rows x 8 segs = 1024 chunks of 16B; 4 per thread per plane
#pragma unroll
    for (int i = 0; i < 4; i++) {
        int idx = tid + i * 256;
        int row = idx >> 3, seg = idx & 7;
        size_t go = (size_t)row * ldk + seg * 8;
        uint32_t sw = (uint32_t)(row * 128) + (uint32_t)((seg ^ (row & 7)) << 4);
        cpasync16(sbase + sw, ah + go);
        cpasync16(sbase + APLANE + sw, al + go);
    }
    // B planes: 256 rows x 8 segs = 2048 chunks; 8 per thread per plane
#pragma unroll
    for (int i = 0; i < 8; i++) {
        int idx = tid + i * 256;
        int row = idx >> 3, seg = idx & 7;
        size_t go = (size_t)row * ldk + seg * 8;
        uint32_t sw = (uint32_t)(row * 128) + (uint32_t)((seg ^ (row & 7)) << 4);
        cpasync16(sbase + 2 * APLANE + sw, bh + go);
        cpasync16(sbase + 2 * APLANE + BPLANE + sw, bl + go);
    }
    asm volatile("cp.async.commit_group;" ::: "memory");
}

template <int KTOT, int EPI>
__global__ void __launch_bounds__(256, 1) hgemm(
    const __nv_bfloat16* __restrict__ Ahi, const __nv_bfloat16* __restrict__ Alo, long sA,
    const __nv_bfloat16* __restrict__ Bhi, const __nv_bfloat16* __restrict__ Blo, long sB,
    const float* __restrict__ bias,
    __nv_bfloat16* __restrict__ Ohi, __nv_bfloat16* __restrict__ Olo,
    float* __restrict__ mp) {
    extern __shared__ __align__(1024) char smem[];
    uint32_t sb = s2u(smem);
    const int tid = threadIdx.x, lane = tid & 31, wid = tid >> 5;
    const int nT = blockIdx.x, mT = blockIdx.y, b = blockIdx.z;
    const int mBase = mT * 128, nBase = nT * 256;
    const int m0 = (wid & 1) * 64, n0w = (wid >> 1) * 64;

    const __nv_bfloat16* pAh = Ahi + (size_t)b * sA + (size_t)mBase * KTOT;
    const __nv_bfloat16* pAl = Alo + (size_t)b * sA + (size_t)mBase * KTOT;
    const __nv_bfloat16* pBh = Bhi + (size_t)b * sB + (size_t)nBase * KTOT;
    const __nv_bfloat16* pBl = Blo + (size_t)b * sB + (size_t)nBase * KTOT;

    constexpr int NCH = KTOT / 64;
    issue_chunk(sb, tid, pAh, pAl, pBh, pBl, KTOT);
    issue_chunk(sb + STAGE, tid, pAh + 64, pAl + 64, pBh + 64, pBl + 64, KTOT);

    float acc[4][8][4] = {};

    const uint32_t aoff0 = (uint32_t)(m0 + (lane & 15)) * 128;
    const int ax = lane & 7, kb = lane >> 4;
    const int grp = lane >> 3;
    const int brow0 = n0w + (lane & 7) + ((grp & 2) << 2);
    const uint32_t boff0 = (uint32_t)brow0 * 128;
    const int bx = brow0 & 7, kgb = grp & 1;

    for (int c = 0; c < NCH; c++) {
        if (c + 1 < NCH) asm volatile("cp.async.wait_group 1;" ::: "memory");
        else             asm volatile("cp.async.wait_group 0;" ::: "memory");
        __syncthreads();

        uint32_t s0 = sb + (c & 1) * STAGE;
#pragma unroll
        for (int ks = 0; ks < 4; ks++) {
            uint32_t ah[4][4], al[4][4];
            const uint32_t kxa = (uint32_t)((((ks << 1) | kb)) ^ ax) << 4;
#pragma unroll
            for (int mt = 0; mt < 4; mt++) {
                uint32_t addr = s0 + aoff0 + mt * 2048 + kxa;
                ldsm4(addr, ah[mt]);
                ldsm4(addr + APLANE, al[mt]);
            }
            const uint32_t kxb = (uint32_t)((((ks << 1) | kgb)) ^ bx) << 4;
#pragma unroll
            for (int np = 0; np < 4; np++) {
                uint32_t bh[4], bl[4];
                uint32_t baddr = s0 + 2 * APLANE + boff0 + np * 2048 + kxb;
                ldsm4(baddr, bh);
                ldsm4(baddr + BPLANE, bl);
#pragma unroll
                for (int mt = 0; mt < 4; mt++) {
#pragma unroll
                    for (int j = 0; j < 2; j++) {
                        float* d = acc[mt][np * 2 + j];
                        mma16816(d, ah[mt], bh + 2 * j);
                        mma16816(d, ah[mt], bl + 2 * j);
                        mma16816(d, al[mt], bh + 2 * j);
                    }
                }
            }
        }
        __syncthreads();
        if (c + 2 < NCH)
            issue_chunk(sb + (c & 1) * STAGE, tid,
                        pAh + (c + 2) * 64, pAl + (c + 2) * 64,
                        pBh + (c + 2) * 64, pBl + (c + 2) * 64, KTOT);
    }

    // accum -> padded fp32 smem (128 x 256, stride PADW)
    float* fsm = (float*)smem;
    {
        const int r0 = lane >> 2, c0 = (lane & 3) * 2;
#pragma unroll
        for (int mt = 0; mt < 4; mt++)
#pragma unroll
            for (int nt = 0; nt < 8; nt++) {
                int rr = m0 + mt * 16 + r0;
                int cc = n0w + nt * 8 + c0;
                fsm[rr * PADW + cc]           = acc[mt][nt][0];
                fsm[rr * PADW + cc + 1]       = acc[mt][nt][1];
                fsm[(rr + 8) * PADW + cc]     = acc[mt][nt][2];
                fsm[(rr + 8) * PADW + cc + 1] = acc[mt][nt][3];
            }
    }
    __syncthreads();

    if constexpr (EPI == 0) {
        // relu + hi/lo row-major out
        const int row = tid >> 1, half = (tid & 1) * 128;
        const float* src = fsm + row * PADW + half;
        size_t go = ((size_t)(b * N_ + mBase + row)) * H_ + nBase + half;
#pragma unroll
        for (int q = 0; q < 16; q++) {
            uint32_t hp[4], lp[4];
#pragma unroll
            for (int j = 0; j < 4; j++) {
                float v0 = fmaxf(src[q * 8 + j * 2], 0.0f);
                float v1 = fmaxf(src[q * 8 + j * 2 + 1], 0.0f);
                __nv_bfloat16 h0, l0, h1, l1;
                split_bf(v0, h0, l0); split_bf(v1, h1, l1);
                hp[j] = pack2(h0, h1); lp[j] = pack2(l0, l1);
            }
            *(uint4*)(Ohi + go + q * 8) = make_uint4(hp[0], hp[1], hp[2], hp[3]);
            *(uint4*)(Olo + go + q * 8) = make_uint4(lp[0], lp[1], lp[2], lp[3]);
        }
    } else if constexpr (EPI == 1) {
        // bias + hi/lo transposed ([N,K]) out; thread = one n row of 128 m
        const int n = tid;
        const float bv = bias[nBase + n];
        size_t go = ((size_t)(b * H_ + nBase + n)) * N_ + mBase;
#pragma unroll
        for (int q = 0; q < 16; q++) {
            uint32_t hp[4], lp[4];
#pragma unroll
            for (int j = 0; j < 4; j++) {
                float v0 = fsm[(q * 8 + j * 2) * PADW + n] + bv;
                float v1 = fsm[(q * 8 + j * 2 + 1) * PADW + n] + bv;
                __nv_bfloat16 h0, l0, h1, l1;
                split_bf(v0, h0, l0); split_bf(v1, h1, l1);
                hp[j] = pack2(h0, h1); lp[j] = pack2(l0, l1);
            }
            *(uint4*)(Ohi + go + q * 8) = make_uint4(hp[0], hp[1], hp[2], hp[3]);
            *(uint4*)(Olo + go + q * 8) = make_uint4(lp[0], lp[1], lp[2], lp[3]);
        }
    } else {
        // relu + partial column sums (mean path)
        const int col = tid;
        float s = 0.0f;
#pragma unroll 16
        for (int r = 0; r < 128; r++)
            s += fmaxf(fsm[r * PADW + col], 0.0f);
        mp[((size_t)mT * B_ + b) * H_ + nBase + col] = s;
    }
}

// ---------------------------------------------------------------------------
// Fused z reductions: y<8 -> rowsum strip; else colsum chunk. grid (B_,16)x256
// ---------------------------------------------------------------------------
__global__ void zsums_kernel(const float* __restrict__ z) {
    int b = blockIdx.x;
    const float* Z = z + (size_t)b * N_ * N_;
    int lane = threadIdx.x & 31, w = threadIdx.x >> 5;
    if (blockIdx.y < 8) {
        int strip = blockIdx.y;
#pragma unroll
        for (int rr = 0; rr < 4; rr++) {
            int row = strip * 32 + w * 4 + rr;
            const float* R = Z + (size_t)row * N_;
            float s = 0.0f;
#pragma unroll
            for (int c = 0; c < 8; c++) s += sigmoidf_(R[lane + 32 * c]);
#pragma unroll
            for (int o = 16; o; o >>= 1) s += __shfl_down_sync(0xffffffffu, s, o);
            if (lane == 0) g_rowsum[b * N_ + row] = s;
        }
    } else {
        int chunk = blockIdx.y - 8;
        int col = chunk * 32 + lane;
        float s = 0.0f;
#pragma unroll 8
        for (int r = 0; r < 32; r++)
            s += sigmoidf_(Z[(size_t)(w * 32 + r) * N_ + col]);
        __shared__ float red[8][32];
        red[w][lane] = s;
        __syncthreads();
        if (w == 0) {
            float t = red[0][lane];
#pragma unroll
            for (int k = 1; k < 8; k++) t += red[k][lane];
            g_colsum[b * N_ + col] = t;
        }
    }
}

// ---------------------------------------------------------------------------
// Fused prep: blocks [0,128): XW1^T (2 nodes/block); [128,384): w2^T tile;
// [384,640): w3^T tile. 1024 threads.
// ---------------------------------------------------------------------------
__global__ void prep_kernel(const float* __restrict__ X, const float* __restrict__ w1,
                            const float* __restrict__ b1,
                            const float* __restrict__ w2, const float* __restrict__ w3) {
    int bx = blockIdx.x, tid = threadIdx.x;
    if (bx < 128) {
        int i = bx * 2 + (tid >> 9);   // node
        int h = tid & 511;
        __shared__ float xr[2][F_];
        if (h < F_) xr[tid >> 9][h] = X[i * F_ + h];
        __syncthreads();
        float acc = b1[h];
#pragma unroll 8
        for (int k = 0; k < F_; k++) acc = fmaf(xr[tid >> 9][k], w1[k * H_ + h], acc);
        __nv_bfloat16 hi, lo;
        split_bf(acc, hi, lo);
        g_XW1thi[h * N_ + i] = hi;
        g_XW1tlo[h * N_ + i] = lo;
    } else {
        const float* w = (bx < 384) ? w2 : w3;
        __nv_bfloat16* thi = (bx < 384) ? g_w2thi : g_w3thi;
        __nv_bfloat16* tlo = (bx < 384) ? g_w2tlo : g_w3tlo;
        int t = (bx < 384) ? bx - 128 : bx - 384;
        int n0 = (t & 15) * 32, k0 = (t >> 4) * 32;
        int tx = tid & 31, ty = tid >> 5;
        __shared__ float tt[32][33];
        tt[ty][tx] = w[(k0 + ty) * H_ + n0 + tx];
        __syncthreads();
        float v = tt[tx][ty];
        __nv_bfloat16 hi, lo;
        split_bf(v, hi, lo);
        thi[(n0 + ty) * H_ + k0 + tx] = hi;
        tlo[(n0 + ty) * H_ + k0 + tx] = lo;
    }
}

// ---------------------------------------------------------------------------
// normA symmetric tile-pair kernel with inline dinv. z read once.
// grid (36 upper-tri block pairs, B_), block 32x32.
// ---------------------------------------------------------------------------
__global__ void norma_kernel(const float* __restrict__ z) {
    int p = blockIdx.x, b = blockIdx.y;
    int bi = 0, rem = p;
    while (rem >= 8 - bi) { rem -= 8 - bi; bi++; }
    int bj = bi + rem;
    int i0 = bi * 32, j0 = bj * 32;
    int tx = threadIdx.x, ty = threadIdx.y;
    __shared__ float tA[32][33];   // sig(z[I,J])
    __shared__ float tB[32][33];   // sig(z[J,I])
    const float* Z = z + (size_t)b * N_ * N_;
    tA[ty][tx] = sigmoidf_(Z[(size_t)(i0 + ty) * N_ + j0 + tx]);
    if (bi != bj) tB[ty][tx] = sigmoidf_(Z[(size_t)(j0 + ty) * N_ + i0 + tx]);
    __syncthreads();
    const float di = dinv_of(b, i0 + ty);
    const float djA = dinv_of(b, j0 + tx);
    {
        float zt = (bi == bj) ? tA[tx][ty] : tB[tx][ty];
        float v = 0.5f * (tA[ty][tx] + zt);
        if (i0 + ty == j0 + tx) v += 1.0f;
        v *= di * djA;
        __nv_bfloat16 h, l; split_bf(v, h, l);
        size_t o = (size_t)b * N_ * N_ + (size_t)(i0 + ty) * N_ + j0 + tx;
        g_nAhi[o] = h; g_nAlo[o] = l;
    }
    if (bi != bj) {
        const float di2 = dinv_of(b, j0 + ty);
        const float dj2 = dinv_of(b, i0 + tx);
        float v = 0.5f * (tB[ty][tx] + tA[tx][ty]);
        v *= di2 * dj2;
        __nv_bfloat16 h, l; split_bf(v, h, l);
        size_t o = (size_t)b * N_ * N_ + (size_t)(j0 + ty) * N_ + i0 + tx;
        g_nAhi[o] = h; g_nAlo[o] = l;
    }
}

// ---------------------------------------------------------------------------
// logits from meanpart
// ---------------------------------------------------------------------------
__global__ void readout_kernel(const float* __restrict__ fcw, const float* __restrict__ fcb,
                               float* __restrict__ out) {
    int b = blockIdx.x;
    int h = threadIdx.x;
    float ge = (g_meanpart[b * H_ + h] + g_meanpart[B_ * H_ + b * H_ + h]) * (1.0f / N_);
    __shared__ float s0[H_], s1[H_];
    s0[h] = ge * fcw[h * 2 + 0];
    s1[h] = ge * fcw[h * 2 + 1];
    __syncthreads();
    for (int st = 256; st > 0; st >>= 1) {
        if (h < st) { s0[h] += s0[h + st]; s1[h] += s1[h + st]; }
        __syncthreads();
    }
    if (h == 0) {
        out[b * 2 + 0] = s0[0] + fcb[0];
        out[b * 2 + 1] = s1[0] + fcb[1];
    }
}

// ---------------------------------------------------------------------------
extern "C" void kernel_launch(void* const* d_in, const int* in_sizes, int n_in,
                              void* d_out, int out_size) {
    const float* z   = (const float*)d_in[0];
    const float* ne  = (const float*)d_in[1];
    const float* w1  = (const float*)d_in[2];
    const float* b1  = (const float*)d_in[3];
    const float* w2  = (const float*)d_in[4];
    const float* b2  = (const float*)d_in[5];
    const float* w3  = (const float*)d_in[6];
    const float* b3  = (const float*)d_in[7];
    const float* fcw = (const float*)d_in[8];
    const float* fcb = (const float*)d_in[9];
    float* out = (float*)d_out;

    __nv_bfloat16 *pnAhi, *pnAlo, *pHhi, *pHlo, *pYthi, *pYtlo;
    __nv_bfloat16 *pXW1thi, *pXW1tlo, *pw2thi, *pw2tlo, *pw3thi, *pw3tlo;
    float* pmean;
    cudaGetSymbolAddress((void**)&pnAhi, g_nAhi);
    cudaGetSymbolAddress((void**)&pnAlo, g_nAlo);
    cudaGetSymbolAddress((void**)&pHhi, g_Hhi);
    cudaGetSymbolAddress((void**)&pHlo, g_Hlo);
    cudaGetSymbolAddress((void**)&pYthi, g_Ythi);
    cudaGetSymbolAddress((void**)&pYtlo, g_Ytlo);
    cudaGetSymbolAddress((void**)&pXW1thi, g_XW1thi);
    cudaGetSymbolAddress((void**)&pXW1tlo, g_XW1tlo);
    cudaGetSymbolAddress((void**)&pw2thi, g_w2thi);
    cudaGetSymbolAddress((void**)&pw2tlo, g_w2tlo);
    cudaGetSymbolAddress((void**)&pw3thi, g_w3thi);
    cudaGetSymbolAddress((void**)&pw3tlo, g_w3tlo);
    cudaGetSymbolAddress((void**)&pmean, g_meanpart);

    cudaFuncSetAttribute(hgemm<256, 0>, cudaFuncAttributeMaxDynamicSharedMemorySize, SMEM_G);
    cudaFuncSetAttribute(hgemm<512, 1>, cudaFuncAttributeMaxDynamicSharedMemorySize, SMEM_G);
    cudaFuncSetAttribute(hgemm<256, 2>, cudaFuncAttributeMaxDynamicSharedMemorySize, SMEM_G);

    zsums_kernel<<<dim3(B_, 16), 256>>>(z);                 // launch 1
    prep_kernel<<<640, 1024>>>(ne, w1, b1, w2, w3);         // launch 2
    norma_kernel<<<dim3(36, B_), dim3(32, 32)>>>(z);        // launch 3

    dim3 gg(2, 2, B_);   // nT (256-wide), mT (128-tall), batch
    // H1 = relu(normA @ XW1)                                // launch 4 (profiled)
    hgemm<256, 0><<<gg, 256, SMEM_G>>>(pnAhi, pnAlo, (long)N_ * N_,
                                       pXW1thi, pXW1tlo, 0, nullptr,
                                       pHhi, pHlo, nullptr);
    // Y2^T = (H1 @ w2 + b2)^T
    hgemm<512, 1><<<gg, 256, SMEM_G>>>(pHhi, pHlo, (long)N_ * H_,
                                       pw2thi, pw2tlo, 0, b2,
                                       pYthi, pYtlo, nullptr);
    // H2 = relu(normA @ Y2)
    hgemm<256, 0><<<gg, 256, SMEM_G>>>(pnAhi, pnAlo, (long)N_ * N_,
                                       pYthi, pYtlo, (long)H_ * N_, nullptr,
                                       pHhi, pHlo, nullptr);
    // Y3^T = (H2 @ w3 + b3)^T
    hgemm<512, 1><<<gg, 256, SMEM_G>>>(pHhi, pHlo, (long)N_ * H_,
                                       pw3thi, pw3tlo, 0, b3,
                                       pYthi, pYtlo, nullptr);
    // meanpart = colsum(relu(normA @ Y3)) per m-tile
    hgemm<256, 2><<<gg, 256, SMEM_G>>>(pnAhi, pnAlo, (long)N_ * N_,
                                       pYthi, pYtlo, (long)H_ * N_, nullptr,
                                       nullptr, nullptr, pmean);

    readout_kernel<<<B_, H_>>>(fcw, fcb, out);
}